// round 3
// baseline (speedup 1.0000x reference)
#include <cuda_runtime.h>
#include <cstddef>

#define TSTEPS 512
#define INDIM  22
#define HDIM   64
#define NTHR   512
#define NBLK   152
#define MROW   28           // padded rows per block (real: 26 or 27)
#define KX     24           // x-part k slots (22 real + 2 zero)
#define KTOT   88           // 24 + 64

// smem floats
#define SM_W    (KTOT * 256)       // 22528  gate-interleaved weights [k][unit*4+gate]
#define SM_B    256
#define SM_ACT  (MROW * KTOT * 2)  // 4928   duplicated-pair activations [row][k]
#define SMEM_FLOATS (SM_W + SM_B + 2 * SM_ACT)
#define SMEM_BYTES  (SMEM_FLOATS * 4)

typedef unsigned long long ull;

__device__ __forceinline__ void ffma2(ull& d, ull a, ull b) {
    asm("fma.rn.f32x2 %0, %1, %2, %0;" : "+l"(d) : "l"(a), "l"(b));
}
__device__ __forceinline__ ull pack2(float lo, float hi) {
    ull r; asm("mov.b64 %0, {%1, %2};" : "=l"(r) : "f"(lo), "f"(hi)); return r;
}
__device__ __forceinline__ void unpack2(ull v, float& lo, float& hi) {
    asm("mov.b64 {%0, %1}, %2;" : "=f"(lo), "=f"(hi) : "l"(v));
}
__device__ __forceinline__ float sigf(float x) {
    return __fdividef(1.0f, 1.0f + __expf(-x));
}
__device__ __forceinline__ float tanh_fast(float x) {
    return __fdividef(2.0f, 1.0f + __expf(-2.0f * x)) - 1.0f;
}

// Compute gates + LSTM cell for NR rows owned by this thread.
template<int NR>
__device__ __forceinline__ void do_rows(
    const ulonglong2* __restrict__ A,   // act buffer (dup pairs), current step
    ull* __restrict__ Nx,               // act buffer for next step
    const ulonglong2* __restrict__ Wq,  // weights, ulonglong2 = 4 gates @ one k
    int tx, int r0, ull bif, ull bgo,
    float* c, float* outp, int M, int t)
{
    ull acc0[NR], acc1[NR];
#pragma unroll
    for (int r = 0; r < NR; r++) { acc0[r] = bif; acc1[r] = bgo; }

#pragma unroll 4
    for (int kp = 0; kp < KTOT / 2; kp++) {
        ulonglong2 wA = Wq[(2 * kp) * 64 + tx];       // ((Wi,Wf),(Wg,Wo)) @ k
        ulonglong2 wB = Wq[(2 * kp + 1) * 64 + tx];   // @ k+1
#pragma unroll
        for (int r = 0; r < NR; r++) {
            ulonglong2 a = A[(r0 + r) * (KTOT / 2) + kp];  // broadcast LDS.128
            ffma2(acc0[r], a.x, wA.x);
            ffma2(acc1[r], a.x, wA.y);
            ffma2(acc0[r], a.y, wB.x);
            ffma2(acc1[r], a.y, wB.y);
        }
    }

#pragma unroll
    for (int r = 0; r < NR; r++) {
        float gi, gf, gg, go;
        unpack2(acc0[r], gi, gf);
        unpack2(acc1[r], gg, go);
        float iv = sigf(gi);
        float fv = sigf(gf);
        float gv = tanh_fast(gg);
        float ov = sigf(go);
        float cn = fmaf(fv, c[r], iv * gv);
        c[r] = cn;
        float h = ov * tanh_fast(cn);
        Nx[(r0 + r) * KTOT + KX + tx] = pack2(h, h);     // conflict-free STS.64
        if (r0 + r < M)
            outp[(size_t)r * TSTEPS * HDIM + (size_t)t * HDIM] = h;  // coalesced
    }
}

__global__ __launch_bounds__(NTHR, 1)
void lstm_persistent_kernel(const float* __restrict__ in,
                            const float* __restrict__ Wih,
                            const float* __restrict__ Whh,
                            const float* __restrict__ bih,
                            const float* __restrict__ bhh,
                            float* __restrict__ out)
{
    extern __shared__ float sm[];
    float* Wsm  = sm;                 // [KTOT][256]
    float* bsm  = Wsm + SM_W;         // [256] interleaved
    float* act0 = bsm + SM_B;
    float* act1 = act0 + SM_ACT;

    const int tid = threadIdx.x;
    const int bid = blockIdx.x;

    // 4096 = 144*27 + 8*26
    const int M        = (bid < 144) ? 27 : 26;
    const int rowStart = (bid < 144) ? bid * 27 : 144 * 27 + (bid - 144) * 26;

    // ---- prologue ----
    for (int i = tid; i < SM_W;       i += NTHR) Wsm[i]  = 0.0f;
    for (int i = tid; i < 2 * SM_ACT; i += NTHR) act0[i] = 0.0f;
    __syncthreads();

    for (int i = tid; i < 256 * INDIM; i += NTHR) {
        int gr = i / INDIM, k = i - gr * INDIM;
        int u = gr & 63, gate = gr >> 6;
        Wsm[k * 256 + u * 4 + gate] = Wih[i];
    }
    for (int i = tid; i < 256 * HDIM; i += NTHR) {
        int gr = i >> 6, k = i & 63;
        int u = gr & 63, gate = gr >> 6;
        Wsm[(KX + k) * 256 + u * 4 + gate] = Whh[i];
    }
    for (int i = tid; i < 256; i += NTHR) {
        int u = i & 63, gate = i >> 6;
        bsm[u * 4 + gate] = bih[i] + bhh[i];
    }

    // ---- x feed slots: 2 scalars per thread covers M*INDIM <= 594 ----
    const int NXL = 2;
    const float* xp[NXL];
    int  sx[NXL];
    bool xv[NXL];
#pragma unroll
    for (int q = 0; q < NXL; q++) {
        int idx = tid + q * NTHR;
        xv[q] = (idx < M * INDIM);
        int r  = idx / INDIM;
        int i2 = idx - r * INDIM;
        sx[q] = r * KTOT + i2;
        xp[q] = xv[q] ? (in + (size_t)(rowStart + r) * TSTEPS * INDIM + i2) : in;
    }

    // mapping: tx = h-unit, rg = row group (uneven: 4 rows for rg<4, else 3)
    const int tx = tid & 63;
    const int rg = tid >> 6;
    const int r0 = (rg < 4) ? rg * 4 : 16 + (rg - 4) * 3;

    float c[4] = {0.0f, 0.0f, 0.0f, 0.0f};

    __syncthreads();

    // x(t=0) into act0
#pragma unroll
    for (int q = 0; q < NXL; q++)
        if (xv[q]) { float v = xp[q][0]; ((ull*)act0)[sx[q]] = pack2(v, v); }

    const ull bif = ((const ull*)bsm)[tx * 2];
    const ull bgo = ((const ull*)bsm)[tx * 2 + 1];
    const ulonglong2* Wq = (const ulonglong2*)Wsm;
    float* outp = out + ((size_t)(rowStart + r0) * TSTEPS) * HDIM + tx;

    __syncthreads();

    // ================= main recurrence =================
    for (int t = 0; t < TSTEPS; t++) {
        const ulonglong2* A  = (const ulonglong2*)((t & 1) ? act1 : act0);
        ull*              Nx = (ull*)((t & 1) ? act0 : act1);

        // prefetch x(t+1)
        float xr[NXL];
        if (t + 1 < TSTEPS) {
#pragma unroll
            for (int q = 0; q < NXL; q++)
                xr[q] = xv[q] ? xp[q][(size_t)(t + 1) * INDIM] : 0.0f;
        }

        if (rg < 4)
            do_rows<4>(A, Nx, Wq, tx, r0, bif, bgo, c, outp, M, t);
        else
            do_rows<3>(A, Nx, Wq, tx, r0, bif, bgo, c, outp, M, t);

        // publish x(t+1)
        if (t + 1 < TSTEPS) {
#pragma unroll
            for (int q = 0; q < NXL; q++)
                if (xv[q]) Nx[sx[q]] = pack2(xr[q], xr[q]);
        }
        __syncthreads();
    }
}

extern "C" void kernel_launch(void* const* d_in, const int* in_sizes, int n_in,
                              void* d_out, int out_size)
{
    const float* in  = (const float*)d_in[0];
    const float* Wih = (const float*)d_in[1];
    const float* Whh = (const float*)d_in[2];
    const float* bih = (const float*)d_in[3];
    const float* bhh = (const float*)d_in[4];
    float* out = (float*)d_out;

    cudaFuncSetAttribute(lstm_persistent_kernel,
                         cudaFuncAttributeMaxDynamicSharedMemorySize, SMEM_BYTES);

    lstm_persistent_kernel<<<NBLK, NTHR, SMEM_BYTES>>>(in, Wih, Whh, bih, bhh, out);
}

// round 6
// speedup vs baseline: 4.2079x; 4.2079x over previous
#include <cuda_runtime.h>
#include <cstdint>
#include <cstddef>

#define TSTEPS 512
#define INDIM  22
#define HDIM   64
#define NTHR   256
#define NBLK   152
#define KT     11            // k-tiles of 8: 3 x-tiles (24 cols), 8 h-tiles
#define AGRP   (KT * 2)      // 22 fragment groups (k-tile x m-tile)
#define AF4    (AGRP * 32)   // float4 slots per A buffer (704 = 11264 B)

__device__ __forceinline__ float tf32r(float x) {
    float y; asm("cvt.rna.tf32.f32 %0, %1;" : "=f"(y) : "f"(x)); return y;
}
__device__ __forceinline__ float sigf(float x) {
    return __fdividef(1.0f, 1.0f + __expf(-x));
}
__device__ __forceinline__ float tanh_fast(float x) {
    return __fdividef(2.0f, 1.0f + __expf(-2.0f * x)) - 1.0f;
}

// D += A(16x8,row) * B(8x8,col);  d: float[4], a: float4 (tf32 bits), b0/b1: tf32 floats
#define MMA8(d, a, b0, b1)                                                  \
    asm volatile("mma.sync.aligned.m16n8k8.row.col.f32.tf32.tf32.f32 "      \
        "{%0,%1,%2,%3}, {%4,%5,%6,%7}, {%8,%9}, {%0,%1,%2,%3};"             \
        : "+f"((d)[0]), "+f"((d)[1]), "+f"((d)[2]), "+f"((d)[3])            \
        : "r"(__float_as_uint((a).x)), "r"(__float_as_uint((a).y)),         \
          "r"(__float_as_uint((a).z)), "r"(__float_as_uint((a).w)),         \
          "r"(__float_as_uint(b0)),    "r"(__float_as_uint(b1)))

__global__ __launch_bounds__(NTHR, 1)
void lstm_mma_kernel(const float* __restrict__ in,
                     const float* __restrict__ Wih,
                     const float* __restrict__ Whh,
                     const float* __restrict__ bih,
                     const float* __restrict__ bhh,
                     float* __restrict__ out)
{
    __shared__ float4 Abuf[2][AF4];

    const int tid = threadIdx.x;
    const int bid = blockIdx.x;
    const int w   = tid >> 5;      // warp 0..7 -> unit slab w*8..w*8+7
    const int l   = tid & 31;

    const int R        = (bid < 144) ? 27 : 26;     // 4096 = 144*27 + 8*26
    const int rowStart = (bid < 144) ? bid * 27 : 144 * 27 + (bid - 144) * 26;

    // ---- zero both A buffers (padding rows/cols stay zero forever) ----
    for (int i = tid; i < 2 * AF4; i += NTHR)
        ((float4*)Abuf)[i] = make_float4(0.f, 0.f, 0.f, 0.f);

    // ---- load B fragments (weights) into registers, tf32-rounded ----
    // b0 = W[n][k], b1 = W[n][k+4]; n = nt*64 + w*8 + l/4; k = kt*8 + l%4
    float bw[KT][4][2];
    {
        const int nu = w * 8 + (l >> 2);
        const int kk = l & 3;
#pragma unroll
        for (int kt = 0; kt < KT; kt++) {
#pragma unroll
            for (int nt = 0; nt < 4; nt++) {
                const int n = nt * 64 + nu;
                if (kt < 3) {
                    int k0 = kt * 8 + kk, k1 = k0 + 4;
                    bw[kt][nt][0] = (k0 < INDIM) ? tf32r(Wih[n * INDIM + k0]) : 0.f;
                    bw[kt][nt][1] = (k1 < INDIM) ? tf32r(Wih[n * INDIM + k1]) : 0.f;
                } else {
                    int k0 = (kt - 3) * 8 + kk;
                    bw[kt][nt][0] = tf32r(Whh[n * HDIM + k0]);
                    bw[kt][nt][1] = tf32r(Whh[n * HDIM + k0 + 4]);
                }
            }
        }
    }

    // ---- biases for this lane's two units (pre-folded into acc init) ----
    const int u0 = w * 8 + 2 * (l & 3);
    float bb[4][2];
#pragma unroll
    for (int g = 0; g < 4; g++) {
        bb[g][0] = bih[g * 64 + u0]     + bhh[g * 64 + u0];
        bb[g][1] = bih[g * 64 + u0 + 1] + bhh[g * 64 + u0 + 1];
    }

    // ---- h write-back float-indices into A fragment layout ----
    // value at (rel-row rr in m16, m-tile mt, k-col kcol, k-tile kt):
    //   fidx = ((kt*2+mt)*32 + (rr&7)*4 + (kcol&3))*4 + ((kcol>>2)*2 | (rr>>3))
    int hoffi[2][2][2];
#pragma unroll
    for (int mt = 0; mt < 2; mt++)
#pragma unroll
        for (int rh = 0; rh < 2; rh++)
#pragma unroll
            for (int j = 0; j < 2; j++) {
                int kcol = (u0 + j) & 7;          // u0..u0+1 within slab
                int ktH  = 3 + w;                 // this warp's h k-tile
                int lanep = (l >> 2) * 4 + (kcol & 3);
                int slot  = ((kcol >> 2) << 1) | rh;
                hoffi[mt][rh][j] = ((ktH * 2 + mt) * 32 + lanep) * 4 + slot;
            }

    // ---- x feed slots (3 per thread covers R*INDIM <= 594) ----
    const int NXL = 3;
    const float* xp[NXL];
    bool xv[NXL];
    int  xoff[NXL];
#pragma unroll
    for (int q = 0; q < NXL; q++) {
        int idx = tid + q * NTHR;
        xv[q] = (idx < R * INDIM);
        int r  = xv[q] ? idx / INDIM : 0;
        int i2 = xv[q] ? idx - r * INDIM : 0;
        xp[q] = in + (size_t)(rowStart + r) * TSTEPS * INDIM + i2;
        int mt = r >> 4, rr = r & 15, ktx = i2 >> 3, kcol = i2 & 7;
        xoff[q] = ((ktx * 2 + mt) * 32 + (rr & 7) * 4 + (kcol & 3)) * 4
                  + (((kcol >> 2) << 1) | (rr >> 3));
    }

    __syncthreads();

    // ---- stage x(0) into buffer 0 ----
#pragma unroll
    for (int q = 0; q < NXL; q++)
        if (xv[q]) ((float*)Abuf[0])[xoff[q]] = tf32r(xp[q][0]);
    __syncthreads();

    float cst[2][2][2];
#pragma unroll
    for (int i = 0; i < 8; i++) ((float*)cst)[i] = 0.0f;

    float* outp = out + (size_t)rowStart * TSTEPS * HDIM + u0;

    // ================= main recurrence =================
#pragma unroll 1
    for (int t = 0; t < TSTEPS; t++) {
        const float4* Ac = Abuf[t & 1];
        float*        An = (float*)Abuf[(t + 1) & 1];

        // prefetch x(t+1) (hidden behind MMA)
        float xr[NXL];
        if (t + 1 < TSTEPS) {
#pragma unroll
            for (int q = 0; q < NXL; q++)
                xr[q] = xv[q] ? xp[q][(size_t)(t + 1) * INDIM] : 0.0f;
        }

        // ---- gates = bias + [x|h] W^T via 88 HMMA ----
        float acc[2][4][4];
#pragma unroll
        for (int mt = 0; mt < 2; mt++)
#pragma unroll
            for (int nt = 0; nt < 4; nt++)
#pragma unroll
                for (int s = 0; s < 4; s++)
                    acc[mt][nt][s] = bb[nt][s & 1];

#pragma unroll
        for (int kt = 0; kt < KT; kt++) {
            float4 a0 = Ac[(kt * 2 + 0) * 32 + l];
            float4 a1 = Ac[(kt * 2 + 1) * 32 + l];
#pragma unroll
            for (int nt = 0; nt < 4; nt++) {
                MMA8(acc[0][nt], a0, bw[kt][nt][0], bw[kt][nt][1]);
                MMA8(acc[1][nt], a1, bw[kt][nt][0], bw[kt][nt][1]);
            }
        }

        // ---- pointwise LSTM cell, in registers ----
#pragma unroll
        for (int mt = 0; mt < 2; mt++) {
#pragma unroll
            for (int rh = 0; rh < 2; rh++) {
                const int row = mt * 16 + rh * 8 + (l >> 2);
                float h2[2];
#pragma unroll
                for (int j = 0; j < 2; j++) {
                    const int s = rh * 2 + j;
                    float iv = sigf(acc[mt][0][s]);
                    float fv = sigf(acc[mt][1][s]);
                    float gv = tanh_fast(acc[mt][2][s]);
                    float ov = sigf(acc[mt][3][s]);
                    float cn = fmaf(fv, cst[mt][rh][j], iv * gv);
                    cst[mt][rh][j] = cn;
                    h2[j] = ov * tanh_fast(cn);
                    An[hoffi[mt][rh][j]] = tf32r(h2[j]);   // h -> A frag layout
                }
                if (row < R)
                    *(float2*)(outp + (size_t)row * TSTEPS * HDIM + (size_t)t * HDIM)
                        = make_float2(h2[0], h2[1]);
            }
        }

        // publish x(t+1)
        if (t + 1 < TSTEPS) {
#pragma unroll
            for (int q = 0; q < NXL; q++)
                if (xv[q]) An[xoff[q]] = tf32r(xr[q]);
        }
        __syncthreads();
    }
}

extern "C" void kernel_launch(void* const* d_in, const int* in_sizes, int n_in,
                              void* d_out, int out_size)
{
    const float* in  = (const float*)d_in[0];
    const float* Wih = (const float*)d_in[1];
    const float* Whh = (const float*)d_in[2];
    const float* bih = (const float*)d_in[3];
    const float* bhh = (const float*)d_in[4];
    float* out = (float*)d_out;

    lstm_mma_kernel<<<NBLK, NTHR>>>(in, Wih, Whh, bih, bhh, out);
}

// round 7
// speedup vs baseline: 4.8531x; 1.1533x over previous
#include <cuda_runtime.h>
#include <cstdint>
#include <cstddef>

#define TSTEPS 512
#define INDIM  22
#define HDIM   64
#define NTHR   256
#define NBLK   152
#define KT     11            // k-tiles of 8: 3 x-tiles (24 cols), 8 h-tiles
#define AGRP   (KT * 2)      // 22 fragment groups (k-tile x m-tile)
#define AF4    (AGRP * 32)   // float4 slots per A buffer (704 = 11264 B)

__device__ __forceinline__ float tf32r(float x) {
    float y; asm("cvt.rna.tf32.f32 %0, %1;" : "=f"(y) : "f"(x)); return y;
}
__device__ __forceinline__ float tanhapx(float x) {
    float y; asm("tanh.approx.f32 %0, %1;" : "=f"(y) : "f"(x)); return y;
}
__device__ __forceinline__ float sigapx(float x) {
    return fmaf(tanhapx(0.5f * x), 0.5f, 0.5f);
}

// D += A(16x8,row) * B(8x8,col);  d: float[4], a: float4 (tf32 bits), b0/b1: tf32 floats
#define MMA8(d, a, b0, b1)                                                  \
    asm volatile("mma.sync.aligned.m16n8k8.row.col.f32.tf32.tf32.f32 "      \
        "{%0,%1,%2,%3}, {%4,%5,%6,%7}, {%8,%9}, {%0,%1,%2,%3};"             \
        : "+f"((d)[0]), "+f"((d)[1]), "+f"((d)[2]), "+f"((d)[3])            \
        : "r"(__float_as_uint((a).x)), "r"(__float_as_uint((a).y)),         \
          "r"(__float_as_uint((a).z)), "r"(__float_as_uint((a).w)),         \
          "r"(__float_as_uint(b0)),    "r"(__float_as_uint(b1)))

__global__ __launch_bounds__(NTHR, 1)
void lstm_mma_kernel(const float* __restrict__ in,
                     const float* __restrict__ Wih,
                     const float* __restrict__ Whh,
                     const float* __restrict__ bih,
                     const float* __restrict__ bhh,
                     float* __restrict__ out)
{
    __shared__ float4 Abuf[2][AF4];

    const int tid = threadIdx.x;
    const int bid = blockIdx.x;
    const int w   = tid >> 5;      // warp 0..7 -> unit slab w*8..w*8+7
    const int l   = tid & 31;

    const int R        = (bid < 144) ? 27 : 26;     // 4096 = 144*27 + 8*26
    const int rowStart = (bid < 144) ? bid * 27 : 144 * 27 + (bid - 144) * 26;

    // ---- zero both A buffers (padding rows/cols stay zero forever) ----
    for (int i = tid; i < 2 * AF4; i += NTHR)
        ((float4*)Abuf)[i] = make_float4(0.f, 0.f, 0.f, 0.f);

    // ---- load B fragments (weights) into registers, tf32-rounded ----
    // b0 = W[n][k], b1 = W[n][k+4]; n = nt*64 + w*8 + l/4; k = kt*8 + l%4
    float bw[KT][4][2];
    {
        const int nu = w * 8 + (l >> 2);
        const int kk = l & 3;
#pragma unroll
        for (int kt = 0; kt < KT; kt++) {
#pragma unroll
            for (int nt = 0; nt < 4; nt++) {
                const int n = nt * 64 + nu;
                if (kt < 3) {
                    int k0 = kt * 8 + kk, k1 = k0 + 4;
                    bw[kt][nt][0] = (k0 < INDIM) ? tf32r(Wih[n * INDIM + k0]) : 0.f;
                    bw[kt][nt][1] = (k1 < INDIM) ? tf32r(Wih[n * INDIM + k1]) : 0.f;
                } else {
                    int k0 = (kt - 3) * 8 + kk;
                    bw[kt][nt][0] = tf32r(Whh[n * HDIM + k0]);
                    bw[kt][nt][1] = tf32r(Whh[n * HDIM + k0 + 4]);
                }
            }
        }
    }

    // ---- biases for this lane's two units (pre-folded into acc init) ----
    const int u0 = w * 8 + 2 * (l & 3);
    float bb[4][2];
#pragma unroll
    for (int g = 0; g < 4; g++) {
        bb[g][0] = bih[g * 64 + u0]     + bhh[g * 64 + u0];
        bb[g][1] = bih[g * 64 + u0 + 1] + bhh[g * 64 + u0 + 1];
    }

    // ---- h write-back float-indices into A fragment layout ----
    int hoffi[2][2][2];
#pragma unroll
    for (int mt = 0; mt < 2; mt++)
#pragma unroll
        for (int rh = 0; rh < 2; rh++)
#pragma unroll
            for (int j = 0; j < 2; j++) {
                int kcol = (u0 + j) & 7;          // u0..u0+1 within slab
                int ktH  = 3 + w;                 // this warp's h k-tile
                int lanep = (l >> 2) * 4 + (kcol & 3);
                int slot  = ((kcol >> 2) << 1) | rh;
                hoffi[mt][rh][j] = ((ktH * 2 + mt) * 32 + lanep) * 4 + slot;
            }

    // ---- x feed slots (3 per thread covers R*INDIM <= 594) ----
    const int NXL = 3;
    const float* xp[NXL];
    bool xv[NXL];
    int  xoff[NXL];
#pragma unroll
    for (int q = 0; q < NXL; q++) {
        int idx = tid + q * NTHR;
        xv[q] = (idx < R * INDIM);
        int r  = xv[q] ? idx / INDIM : 0;
        int i2 = xv[q] ? idx - r * INDIM : 0;
        xp[q] = in + (size_t)(rowStart + r) * TSTEPS * INDIM + i2;
        int mt = r >> 4, rr = r & 15, ktx = i2 >> 3, kcol = i2 & 7;
        xoff[q] = ((ktx * 2 + mt) * 32 + (rr & 7) * 4 + (kcol & 3)) * 4
                  + (((kcol >> 2) << 1) | (rr >> 3));
    }

    __syncthreads();

    // ---- stage x(0) into buffer 0 ----
#pragma unroll
    for (int q = 0; q < NXL; q++)
        if (xv[q]) ((float*)Abuf[0])[xoff[q]] = tf32r(xp[q][0]);
    __syncthreads();

    float cst[2][2][2];
#pragma unroll
    for (int i = 0; i < 8; i++) ((float*)cst)[i] = 0.0f;

    float* outp = out + (size_t)rowStart * TSTEPS * HDIM + u0;

    // ================= main recurrence =================
#pragma unroll 1
    for (int t = 0; t < TSTEPS; t++) {
        const float4* Ac = Abuf[t & 1];
        float*        An = (float*)Abuf[(t + 1) & 1];

        // prefetch x(t+1) (hidden behind MMA)
        float xr[NXL];
        if (t + 1 < TSTEPS) {
#pragma unroll
            for (int q = 0; q < NXL; q++)
                xr[q] = xv[q] ? xp[q][(size_t)(t + 1) * INDIM] : 0.0f;
        }

        // ---- gates = bias + [x|h] W^T via 88 HMMA ----
        float acc[2][4][4];
#pragma unroll
        for (int mt = 0; mt < 2; mt++)
#pragma unroll
            for (int nt = 0; nt < 4; nt++)
#pragma unroll
                for (int s = 0; s < 4; s++)
                    acc[mt][nt][s] = bb[nt][s & 1];

#pragma unroll
        for (int kt = 0; kt < KT; kt++) {
            float4 a0 = Ac[(kt * 2 + 0) * 32 + l];
            float4 a1 = Ac[(kt * 2 + 1) * 32 + l];
#pragma unroll
            for (int nt = 0; nt < 4; nt++) {
                MMA8(acc[0][nt], a0, bw[kt][nt][0], bw[kt][nt][1]);
                MMA8(acc[1][nt], a1, bw[kt][nt][0], bw[kt][nt][1]);
            }
        }

        // ---- pointwise LSTM cell, in registers (1 MUFU per activation) ----
#pragma unroll
        for (int mt = 0; mt < 2; mt++) {
#pragma unroll
            for (int rh = 0; rh < 2; rh++) {
                const int row = mt * 16 + rh * 8 + (l >> 2);
                float h2[2];
#pragma unroll
                for (int j = 0; j < 2; j++) {
                    const int s = rh * 2 + j;
                    float iv = sigapx(acc[mt][0][s]);
                    float fv = sigapx(acc[mt][1][s]);
                    float gv = tanhapx(acc[mt][2][s]);
                    float ov = sigapx(acc[mt][3][s]);
                    float cn = fmaf(fv, cst[mt][rh][j], iv * gv);
                    cst[mt][rh][j] = cn;
                    h2[j] = ov * tanhapx(cn);
                    An[hoffi[mt][rh][j]] = tf32r(h2[j]);   // h -> A frag layout
                }
                if (row < R)
                    *(float2*)(outp + (size_t)row * TSTEPS * HDIM + (size_t)t * HDIM)
                        = make_float2(h2[0], h2[1]);
            }
        }

        // publish x(t+1)
        if (t + 1 < TSTEPS) {
#pragma unroll
            for (int q = 0; q < NXL; q++)
                if (xv[q]) An[xoff[q]] = tf32r(xr[q]);
        }
        __syncthreads();
    }
}

extern "C" void kernel_launch(void* const* d_in, const int* in_sizes, int n_in,
                              void* d_out, int out_size)
{
    const float* in  = (const float*)d_in[0];
    const float* Wih = (const float*)d_in[1];
    const float* Whh = (const float*)d_in[2];
    const float* bih = (const float*)d_in[3];
    const float* bhh = (const float*)d_in[4];
    float* out = (float*)d_out;

    lstm_mma_kernel<<<NBLK, NTHR>>>(in, Wih, Whh, bih, bhh, out);
}

// round 8
// speedup vs baseline: 6.4839x; 1.3360x over previous
#include <cuda_runtime.h>
#include <cuda_fp16.h>
#include <cstdint>
#include <cstddef>

#define TSTEPS 512
#define INDIM  22
#define HDIM   64
#define NTHR   256
#define NBLK   152
#define KT     6             // k-tiles of 16: 2 x-tiles (32 padded cols), 4 h-tiles
#define AGRP   (KT * 2)      // 12 fragment groups (k-tile x m-tile)
#define AF4    (AGRP * 32)   // float4 slots per A buffer (384 = 6144 B)

__device__ __forceinline__ float tanhapx(float x) {
    float y; asm("tanh.approx.f32 %0, %1;" : "=f"(y) : "f"(x)); return y;
}
__device__ __forceinline__ float sigapx(float x) {
    return fmaf(tanhapx(0.5f * x), 0.5f, 0.5f);
}
__device__ __forceinline__ uint32_t packh2(float lo, float hi) {
    __half2 h = __floats2half2_rn(lo, hi);
    return *(uint32_t*)&h;
}

// D += A(16x16,row) * B(16x8,col); fp16 inputs, f32 accum
#define MMA16(d, a, b0, b1)                                                 \
    asm volatile("mma.sync.aligned.m16n8k16.row.col.f32.f16.f16.f32 "       \
        "{%0,%1,%2,%3}, {%4,%5,%6,%7}, {%8,%9}, {%0,%1,%2,%3};"             \
        : "+f"((d)[0]), "+f"((d)[1]), "+f"((d)[2]), "+f"((d)[3])            \
        : "r"(__float_as_uint((a).x)), "r"(__float_as_uint((a).y)),         \
          "r"(__float_as_uint((a).z)), "r"(__float_as_uint((a).w)),         \
          "r"(b0), "r"(b1))

__global__ __launch_bounds__(NTHR, 1)
void lstm_mma_kernel(const float* __restrict__ in,
                     const float* __restrict__ Wih,
                     const float* __restrict__ Whh,
                     const float* __restrict__ bih,
                     const float* __restrict__ bhh,
                     float* __restrict__ out)
{
    __shared__ float4 Abuf[2][AF4];

    const int tid = threadIdx.x;
    const int bid = blockIdx.x;
    const int w   = tid >> 5;      // warp 0..7 -> unit slab w*8..w*8+7
    const int l   = tid & 31;

    const int R        = (bid < 144) ? 27 : 26;     // 4096 = 144*27 + 8*26
    const int rowStart = (bid < 144) ? bid * 27 : 144 * 27 + (bid - 144) * 26;

    // ---- zero both A buffers (padding rows/cols stay zero forever) ----
    for (int i = tid; i < 2 * AF4; i += NTHR)
        ((float4*)Abuf)[i] = make_float4(0.f, 0.f, 0.f, 0.f);

    // ---- load B fragments (fp16 weights) into registers ----
    // lane l: n = nt*64 + w*8 + l/4 ; k0 = (l%4)*2
    // b0 = half2(W[n][k0], W[n][k0+1]) ; b1 = half2(W[n][k0+8], W[n][k0+9])
    uint32_t bw[KT][4][2];
    {
        const int nu = w * 8 + (l >> 2);
        const int k0 = (l & 3) * 2;
#pragma unroll
        for (int kt = 0; kt < KT; kt++) {
#pragma unroll
            for (int nt = 0; nt < 4; nt++) {
                const int n = nt * 64 + nu;
                if (kt < 2) {                       // x tiles: k = kt*16 + ...
                    int ka = kt * 16 + k0, kb = ka + 8;
                    float a0 = (ka     < INDIM) ? Wih[n * INDIM + ka]     : 0.f;
                    float a1 = (ka + 1 < INDIM) ? Wih[n * INDIM + ka + 1] : 0.f;
                    float b0 = (kb     < INDIM) ? Wih[n * INDIM + kb]     : 0.f;
                    float b1 = (kb + 1 < INDIM) ? Wih[n * INDIM + kb + 1] : 0.f;
                    bw[kt][nt][0] = packh2(a0, a1);
                    bw[kt][nt][1] = packh2(b0, b1);
                } else {                            // h tiles
                    int ka = (kt - 2) * 16 + k0;
                    bw[kt][nt][0] = packh2(Whh[n * HDIM + ka],     Whh[n * HDIM + ka + 1]);
                    bw[kt][nt][1] = packh2(Whh[n * HDIM + ka + 8], Whh[n * HDIM + ka + 9]);
                }
            }
        }
    }

    // ---- biases for this lane's two units (folded into acc init) ----
    const int u0 = w * 8 + 2 * (l & 3);
    float bb[4][2];
#pragma unroll
    for (int g = 0; g < 4; g++) {
        bb[g][0] = bih[g * 64 + u0]     + bhh[g * 64 + u0];
        bb[g][1] = bih[g * 64 + u0 + 1] + bhh[g * 64 + u0 + 1];
    }

    // ---- h write-back u32 slots (half2 covering units u0,u0+1) ----
    // h k-tile: ktH = 2 + u0/16, tile-col tc = u0 & 15 (even)
    // lane' = (l>>2)*4 + ((tc&7)>>1) ; slot = rh | ((tc>>3)<<1)
    int hoff[2][2];
    {
        const int ktH = 2 + (u0 >> 4);
        const int tc  = u0 & 15;
        const int lp  = (l >> 2) * 4 + ((tc & 7) >> 1);
#pragma unroll
        for (int mt = 0; mt < 2; mt++)
#pragma unroll
            for (int rh = 0; rh < 2; rh++)
                hoff[mt][rh] = (((ktH * 2 + mt) * 32 + lp) * 4) + (rh | ((tc >> 3) << 1));
    }

    // ---- x feed slots (3 per thread covers R*INDIM <= 594), half-index ----
    const int NXL = 3;
    const float* xp[NXL];
    bool xv[NXL];
    int  xoff[NXL];
#pragma unroll
    for (int q = 0; q < NXL; q++) {
        int idx = tid + q * NTHR;
        xv[q] = (idx < R * INDIM);
        int r  = xv[q] ? idx / INDIM : 0;
        int i2 = xv[q] ? idx - r * INDIM : 0;
        xp[q] = in + (size_t)(rowStart + r) * TSTEPS * INDIM + i2;
        int mt = r >> 4, rr = r & 15, ktx = i2 >> 4, tc = i2 & 15;
        int lp   = (rr & 7) * 4 + ((tc & 7) >> 1);
        int slot = (rr >> 3) | ((tc >> 3) << 1);
        xoff[q] = ((((ktx * 2 + mt) * 32 + lp) * 4) + slot) * 2 + (tc & 1);
    }

    __syncthreads();

    // ---- stage x(0) into buffer 0 ----
#pragma unroll
    for (int q = 0; q < NXL; q++)
        if (xv[q]) ((__half*)Abuf[0])[xoff[q]] = __float2half_rn(xp[q][0]);
    __syncthreads();

    float cst[2][2][2];
#pragma unroll
    for (int i = 0; i < 8; i++) ((float*)cst)[i] = 0.0f;

    float* outp = out + (size_t)rowStart * TSTEPS * HDIM + u0;

    // ================= main recurrence =================
#pragma unroll 1
    for (int t = 0; t < TSTEPS; t++) {
        const float4* Ac = Abuf[t & 1];
        uint32_t*     An = (uint32_t*)Abuf[(t + 1) & 1];

        // prefetch x(t+1) (hidden behind MMA)
        float xr[NXL];
        if (t + 1 < TSTEPS) {
#pragma unroll
            for (int q = 0; q < NXL; q++)
                xr[q] = xv[q] ? xp[q][(size_t)(t + 1) * INDIM] : 0.0f;
        }

        // ---- gates = bias + [x|h] W^T via 48 HMMA (fp16, f32 accum) ----
        float acc[2][4][4];
#pragma unroll
        for (int mt = 0; mt < 2; mt++)
#pragma unroll
            for (int nt = 0; nt < 4; nt++)
#pragma unroll
                for (int s = 0; s < 4; s++)
                    acc[mt][nt][s] = bb[nt][s & 1];

#pragma unroll
        for (int kt = 0; kt < KT; kt++) {
            float4 a0 = Ac[(kt * 2 + 0) * 32 + l];
            float4 a1 = Ac[(kt * 2 + 1) * 32 + l];
#pragma unroll
            for (int nt = 0; nt < 4; nt++) {
                MMA16(acc[0][nt], a0, bw[kt][nt][0], bw[kt][nt][1]);
                MMA16(acc[1][nt], a1, bw[kt][nt][0], bw[kt][nt][1]);
            }
        }

        // ---- pointwise LSTM cell, in registers ----
#pragma unroll
        for (int mt = 0; mt < 2; mt++) {
#pragma unroll
            for (int rh = 0; rh < 2; rh++) {
                const int row = mt * 16 + rh * 8 + (l >> 2);
                float h2[2];
#pragma unroll
                for (int j = 0; j < 2; j++) {
                    const int s = rh * 2 + j;
                    float iv = sigapx(acc[mt][0][s]);
                    float fv = sigapx(acc[mt][1][s]);
                    float gv = tanhapx(acc[mt][2][s]);
                    float ov = sigapx(acc[mt][3][s]);
                    float cn = fmaf(fv, cst[mt][rh][j], iv * gv);
                    cst[mt][rh][j] = cn;
                    h2[j] = ov * tanhapx(cn);
                }
                An[hoff[mt][rh]] = packh2(h2[0], h2[1]);   // h -> A frag (half2)
                if (row < R)
                    *(float2*)(outp + (size_t)row * TSTEPS * HDIM + (size_t)t * HDIM)
                        = make_float2(h2[0], h2[1]);
            }
        }

        // publish x(t+1)
        if (t + 1 < TSTEPS) {
#pragma unroll
            for (int q = 0; q < NXL; q++)
                if (xv[q]) ((__half*)An)[xoff[q]] = __float2half_rn(xr[q]);
        }
        __syncthreads();
    }
}

extern "C" void kernel_launch(void* const* d_in, const int* in_sizes, int n_in,
                              void* d_out, int out_size)
{
    const float* in  = (const float*)d_in[0];
    const float* Wih = (const float*)d_in[1];
    const float* Whh = (const float*)d_in[2];
    const float* bih = (const float*)d_in[3];
    const float* bhh = (const float*)d_in[4];
    float* out = (float*)d_out;

    lstm_mma_kernel<<<NBLK, NTHR>>>(in, Wih, Whh, bih, bhh, out);
}